// round 9
// baseline (speedup 1.0000x reference)
#include <cuda_runtime.h>
#include <cuda_bf16.h>
#include <cstdint>

// ---------------------------------------------------------------------------
// CharRNN: T=16384 LSTM steps, E=H=1024, loss = sum_t (logsumexp(h_t) - h_t[y_t])
//
// Kernel 0: init (zero sync tags + row flags, detect ys dtype)
// Kernel 1: xg GEMM (fp32, f32x2 FMA), split: 24-M-block serial head (full
//           chip) + 104-M-block tail concurrent with the recurrence on the
//           20 SMs the recurrence leaves idle. Per-M-block completion flags.
// Kernel 2: persistent recurrence, 128 CTAs (1/SM); h published as {f32,tag}
//           8B words (fused data+flag, fence-free); weights in registers;
//           f32x2 dots; shfl butterflies; poll backoff to cut L2 storm.
// Kernel 3: parallel per-timestep loss   Kernel 4: deterministic reduction
// ---------------------------------------------------------------------------

#define T_STEPS 16384
#define E_DIM   1024
#define H_DIM   1024
#define NWORK   128
#define NMBLK   (T_STEPS / 128)     // 128 M-blocks of the GEMM
#define NNBLK   (4 * H_DIM / 128)   // 32 N-blocks per M-block
#define MHEAD   24                  // M-blocks computed before the recurrence

typedef unsigned long long ull;

__device__ float      g_xg[(size_t)T_STEPS * 4 * H_DIM];   // 256 MB
__device__ float      g_hist[(size_t)T_STEPS * H_DIM];     // 64 MB
__device__ ulonglong2 g_sync[2][H_DIM / 2];                // {h,tag} pairs, 2x8KB
__device__ unsigned   g_rowflag[NMBLK];                    // GEMM M-block counters
__device__ float      g_loss[T_STEPS];
__device__ int        g_is64;

// ---------------------------------------------------------------------------
__device__ __forceinline__ ull ffma2(ull a, ull b, ull c)
{
    ull d;
    asm("fma.rn.f32x2 %0, %1, %2, %3;" : "=l"(d) : "l"(a), "l"(b), "l"(c));
    return d;
}
__device__ __forceinline__ float2 unpack2(ull v)
{
    float2 f;
    asm("mov.b64 {%0, %1}, %2;" : "=f"(f.x), "=f"(f.y) : "l"(v));
    return f;
}
__device__ __forceinline__ ull pack2(float lo, float hi)
{
    ull v;
    asm("mov.b64 %0, {%1, %2};" : "=l"(v) : "f"(lo), "f"(hi));
    return v;
}
__device__ __forceinline__ float pair_h(ull p)
{
    return __uint_as_float((unsigned)(p & 0xffffffffull));
}
__device__ __forceinline__ float tanh_apx(float x)
{
    float r;
    asm("tanh.approx.f32 %0, %1;" : "=f"(r) : "f"(x));
    return r;
}

// ---------------------------------------------------------------------------
// init: zero sync tags + row flags + detect ys dtype
// ---------------------------------------------------------------------------
__global__ void init_kernel(const int* __restrict__ ys32)
{
    const int tid = threadIdx.x;
    ulonglong2 z = make_ulonglong2(0ull, 0ull);
    for (int i = tid; i < H_DIM / 2; i += 256) {
        g_sync[0][i] = z;
        g_sync[1][i] = z;
    }
    if (tid < NMBLK) g_rowflag[tid] = 0u;
    __shared__ int any_odd;
    if (tid == 0) any_odd = 0;
    __syncthreads();
    int odd = 0;
    for (int i = tid; i < T_STEPS / 2; i += 256)
        odd |= (ys32[2 * i + 1] != 0);
    if (odd) any_odd = 1;
    __syncthreads();
    if (tid == 0) g_is64 = !any_odd;
}

// ---------------------------------------------------------------------------
// GEMM: C[M=T][N=4096] = X[M][K=1024] * W[N][K]^T + (b1+b2), f32x2 inner loop
// m_off selects the M-block window; publishes g_rowflag[m]++ when stored.
// ---------------------------------------------------------------------------
__global__ __launch_bounds__(256, 2) void xg_gemm_kernel(
    const float* __restrict__ X, const float* __restrict__ W,
    const float* __restrict__ b1, const float* __restrict__ b2, int m_off)
{
    __shared__ float As[8][128];
    __shared__ float Bs[8][128];

    const int mb = blockIdx.y + m_off;
    const int bm = mb * 128;
    const int bn = blockIdx.x * 128;
    const int tid = threadIdx.x;
    const int tr = (tid >> 4) << 3;
    const int tc = (tid & 15) << 3;
    const int lr = tid >> 1;
    const int lc = (tid & 1) << 2;

    const float* Ag = X + (size_t)(bm + lr) * E_DIM + lc;
    const float* Bg = W + (size_t)(bn + lr) * E_DIM + lc;

    ull acc2[8][4];
#pragma unroll
    for (int i = 0; i < 8; i++)
#pragma unroll
        for (int j = 0; j < 4; j++) acc2[i][j] = 0ull;

    for (int k0 = 0; k0 < E_DIM; k0 += 8) {
        float4 av = *(const float4*)(Ag + k0);
        float4 bv = *(const float4*)(Bg + k0);
        __syncthreads();
        As[lc + 0][lr] = av.x; As[lc + 1][lr] = av.y;
        As[lc + 2][lr] = av.z; As[lc + 3][lr] = av.w;
        Bs[lc + 0][lr] = bv.x; Bs[lc + 1][lr] = bv.y;
        Bs[lc + 2][lr] = bv.z; Bs[lc + 3][lr] = bv.w;
        __syncthreads();
#pragma unroll
        for (int kk = 0; kk < 8; kk++) {
            float4 b0 = *(const float4*)&Bs[kk][tc];
            float4 b1v = *(const float4*)&Bs[kk][tc + 4];
            ull b2r[4];
            b2r[0] = pack2(b0.x, b0.y); b2r[1] = pack2(b0.z, b0.w);
            b2r[2] = pack2(b1v.x, b1v.y); b2r[3] = pack2(b1v.z, b1v.w);
            float4 a0 = *(const float4*)&As[kk][tr];
            float4 a1v = *(const float4*)&As[kk][tr + 4];
            float ar[8] = {a0.x, a0.y, a0.z, a0.w, a1v.x, a1v.y, a1v.z, a1v.w};
#pragma unroll
            for (int i = 0; i < 8; i++) {
                ull a2 = pack2(ar[i], ar[i]);
#pragma unroll
                for (int j = 0; j < 4; j++)
                    acc2[i][j] = ffma2(a2, b2r[j], acc2[i][j]);
            }
        }
    }

    float bias[8];
#pragma unroll
    for (int j = 0; j < 8; j++) bias[j] = b1[bn + tc + j] + b2[bn + tc + j];

#pragma unroll
    for (int i = 0; i < 8; i++) {
        size_t row = (size_t)(bm + tr + i);
        float* cp = g_xg + row * (4 * H_DIM) + bn + tc;
        float2 p0 = unpack2(acc2[i][0]), p1 = unpack2(acc2[i][1]);
        float2 p2 = unpack2(acc2[i][2]), p3 = unpack2(acc2[i][3]);
        float4 v0, v1;
        v0.x = p0.x + bias[0]; v0.y = p0.y + bias[1];
        v0.z = p1.x + bias[2]; v0.w = p1.y + bias[3];
        v1.x = p2.x + bias[4]; v1.y = p2.y + bias[5];
        v1.z = p3.x + bias[6]; v1.w = p3.y + bias[7];
        *(float4*)(cp + 0) = v0;
        *(float4*)(cp + 4) = v1;
    }

    // release: fence stores, then one thread bumps this M-block's flag
    __threadfence();
    __syncthreads();
    if (tid == 0) atomicAdd(&g_rowflag[mb], 1u);
}

// ---------------------------------------------------------------------------
// persistent recurrence: 128 CTAs x 256 threads; warp w of CTA b owns h index
// k=b*8+w and gate rows {k,H+k,2H+k,3H+k} in registers. Sync = tagged 8B words.
// Poll backoff (nanosleep on miss) cuts redundant L2 traffic.
// ---------------------------------------------------------------------------
__global__ __launch_bounds__(256, 1) void lstm_kernel(const float* __restrict__ W_hh)
{
    const int cta  = blockIdx.x;
    const int tid  = threadIdx.x;
    const int warp = tid >> 5;
    const int lane = tid & 31;
    const int k    = cta * 8 + warp;

    __shared__ float hs[2][H_DIM];          // double-buffered stage

    ull w0[16], w1[16], w2[16], w3[16];
#pragma unroll
    for (int c = 0; c < 8; c++) {
        int col = lane + 32 * c;           // float4 index in row
        ulonglong2 v;
        v = ((const ulonglong2*)(W_hh + (size_t)(0 * H_DIM + k) * H_DIM))[col];
        w0[2 * c] = v.x; w0[2 * c + 1] = v.y;
        v = ((const ulonglong2*)(W_hh + (size_t)(1 * H_DIM + k) * H_DIM))[col];
        w1[2 * c] = v.x; w1[2 * c + 1] = v.y;
        v = ((const ulonglong2*)(W_hh + (size_t)(2 * H_DIM + k) * H_DIM))[col];
        w2[2 * c] = v.x; w2[2 * c + 1] = v.y;
        v = ((const ulonglong2*)(W_hh + (size_t)(3 * H_DIM + k) * H_DIM))[col];
        w3[2 * c] = v.x; w3[2 * c + 1] = v.y;
    }

    float c_state = 0.f;

    float xn = 0.f;
    bool  pf = false;       // xn holds a valid prefetched value for step t
    int   ok_blk = -1;      // highest M-block known complete (per-thread)

    for (int t = 0; t < T_STEPS; t++) {
        // --- xg for this step (lanes 0-3 only) ---
        if (lane < 4 && !pf) {
            while (__ldcg(&g_rowflag[t >> 7]) < (unsigned)NNBLK)
                __nanosleep(200);
            ok_blk = t >> 7;
            xn = __ldcs(g_xg + (size_t)t * (4 * H_DIM) + (size_t)lane * H_DIM + k);
        }
        float xg_j = xn;

        // --- prefetch xg for step t+1 (flag re-checked only at block bounds) ---
        if (lane < 4) {
            pf = false;
            int nt = t + 1;
            if (nt < T_STEPS) {
                int nb = nt >> 7;
                if (nb == ok_blk ||
                    __ldcg(&g_rowflag[nb]) >= (unsigned)NNBLK) {
                    ok_blk = nb;
                    xn = __ldcs(g_xg + (size_t)nt * (4 * H_DIM) +
                                (size_t)lane * H_DIM + k);
                    pf = true;
                }
            } else {
                pf = true;
            }
        }

        float a0 = 0.f, a1 = 0.f, a2 = 0.f, a3 = 0.f;
        if (t > 0) {
            // poll own 4 pairs until tag == t; nanosleep on miss (L2 relief)
            const ulonglong2* sb = g_sync[t & 1];
            const unsigned expt = (unsigned)t;
            ull pa, pb, pc, pd;
            for (;;) {
                asm volatile("ld.global.cg.v2.u64 {%0,%1}, [%2];"
                             : "=l"(pa), "=l"(pb) : "l"(sb + 2 * tid));
                asm volatile("ld.global.cg.v2.u64 {%0,%1}, [%2];"
                             : "=l"(pc), "=l"(pd) : "l"(sb + 2 * tid + 1));
                if ((unsigned)(pa >> 32) == expt && (unsigned)(pb >> 32) == expt &&
                    (unsigned)(pc >> 32) == expt && (unsigned)(pd >> 32) == expt)
                    break;
                __nanosleep(32);
            }
            ((float4*)hs[t & 1])[tid] =
                make_float4(pair_h(pa), pair_h(pb), pair_h(pc), pair_h(pd));
            __syncthreads();   // hs[t&1] ready (single bar per step)

            const ulonglong2* hsv = (const ulonglong2*)hs[t & 1];
            ull p0 = 0, p1 = 0, p2 = 0, p3 = 0;
#pragma unroll
            for (int c = 0; c < 8; c++) {
                ulonglong2 hv = hsv[lane + 32 * c];
                p0 = ffma2(w0[2 * c], hv.x, p0); p0 = ffma2(w0[2 * c + 1], hv.y, p0);
                p1 = ffma2(w1[2 * c], hv.x, p1); p1 = ffma2(w1[2 * c + 1], hv.y, p1);
                p2 = ffma2(w2[2 * c], hv.x, p2); p2 = ffma2(w2[2 * c + 1], hv.y, p2);
                p3 = ffma2(w3[2 * c], hv.x, p3); p3 = ffma2(w3[2 * c + 1], hv.y, p3);
            }
            float2 f;
            f = unpack2(p0); a0 = f.x + f.y;
            f = unpack2(p1); a1 = f.x + f.y;
            f = unpack2(p2); a2 = f.x + f.y;
            f = unpack2(p3); a3 = f.x + f.y;
        }

        // 4x scalar butterfly reductions
#pragma unroll
        for (int off = 16; off; off >>= 1) {
            a0 += __shfl_xor_sync(0xffffffffu, a0, off);
            a1 += __shfl_xor_sync(0xffffffffu, a1, off);
            a2 += __shfl_xor_sync(0xffffffffu, a2, off);
            a3 += __shfl_xor_sync(0xffffffffu, a3, off);
        }

        // lane-parallel activations: lane j in {0..3} computes gate j
        float aj = a0;
        aj = (lane == 1) ? a1 : aj;
        aj = (lane == 2) ? a2 : aj;
        aj = (lane == 3) ? a3 : aj;
        float z   = aj + xg_j;
        float arg = (lane == 2) ? z : 0.5f * z;
        float th  = tanh_apx(arg);
        float gte = (lane == 2) ? th : fmaf(0.5f, th, 0.5f);   // sigmoid via tanh

        float gf = __shfl_sync(0xffffffffu, gte, 1);
        float gg = __shfl_sync(0xffffffffu, gte, 2);
        float go = __shfl_sync(0xffffffffu, gte, 3);

        if (lane == 0) {
            c_state = gf * c_state + gte * gg;       // gte == gi on lane 0
            float h = go * tanh_apx(c_state);
            ull p = ((ull)(unsigned)(t + 1) << 32) | (ull)__float_as_uint(h);
            __stcg(((ull*)g_sync[(t + 1) & 1]) + k, p);
            __stcs(&g_hist[(size_t)t * H_DIM + k], h);
        }
    }
}

// ---------------------------------------------------------------------------
// parallel loss: one CTA per timestep
// ---------------------------------------------------------------------------
__global__ __launch_bounds__(256) void loss_kernel(const int* __restrict__ ys32)
{
    const int t    = blockIdx.x;
    const int tid  = threadIdx.x;
    const int warp = tid >> 5;
    const int lane = tid & 31;
    __shared__ float red[8];

    const float* hrow = g_hist + (size_t)t * H_DIM;
    float4 hv = __ldcs(((const float4*)hrow) + tid);
    float s = __expf(hv.x) + __expf(hv.y) + __expf(hv.z) + __expf(hv.w);
#pragma unroll
    for (int off = 16; off; off >>= 1)
        s += __shfl_xor_sync(0xffffffffu, s, off);
    if (lane == 0) red[warp] = s;
    __syncthreads();
    if (tid == 0) {
        float tot = 0.f;
#pragma unroll
        for (int i = 0; i < 8; i++) tot += red[i];
        int y = g_is64 ? ys32[2 * t] : ys32[t];
        y &= (H_DIM - 1);
        g_loss[t] = logf(tot) - hrow[y];
    }
}

// ---------------------------------------------------------------------------
__global__ __launch_bounds__(256) void reduce_kernel(float* __restrict__ out)
{
    const int tid = threadIdx.x;
    __shared__ double red[256];
    double acc = 0.0;
    for (int i = tid; i < T_STEPS; i += 256)
        acc += (double)g_loss[i];
    red[tid] = acc;
    __syncthreads();
    for (int s = 128; s; s >>= 1) {
        if (tid < s) red[tid] += red[tid + s];
        __syncthreads();
    }
    if (tid == 0) out[0] = (float)red[0];
}

// ---------------------------------------------------------------------------
extern "C" void kernel_launch(void* const* d_in, const int* in_sizes, int n_in,
                              void* d_out, int out_size)
{
    const float* Xs   = (const float*)d_in[0];
    const float* W_ih = (const float*)d_in[1];
    const float* W_hh = (const float*)d_in[2];
    const float* b_ih = (const float*)d_in[3];
    const float* b_hh = (const float*)d_in[4];
    const int*   ys32 = (const int*)d_in[5];
    float* out = (float*)d_out;

    (void)in_sizes; (void)n_in; (void)out_size;

    static cudaStream_t s_gemm = nullptr;
    static cudaEvent_t  ev_fork = nullptr, ev_join = nullptr;
    if (!s_gemm) {
        int least = 0, greatest = 0;
        cudaDeviceGetStreamPriorityRange(&least, &greatest);
        cudaStreamCreateWithPriority(&s_gemm, cudaStreamNonBlocking, least);
        cudaEventCreateWithFlags(&ev_fork, cudaEventDisableTiming);
        cudaEventCreateWithFlags(&ev_join, cudaEventDisableTiming);
    }

    init_kernel<<<1, 256>>>(ys32);

    // serial head: first MHEAD M-blocks on the full chip
    dim3 ghead(NNBLK, MHEAD);
    xg_gemm_kernel<<<ghead, 256>>>(Xs, W_ih, b_ih, b_hh, 0);

    // fork: remaining M-blocks on low-priority stream, recurrence on main
    cudaEventRecord(ev_fork, 0);
    cudaStreamWaitEvent(s_gemm, ev_fork, 0);
    dim3 grest(NNBLK, NMBLK - MHEAD);
    xg_gemm_kernel<<<grest, 256, 0, s_gemm>>>(Xs, W_ih, b_ih, b_hh, MHEAD);

    lstm_kernel<<<NWORK, 256>>>(W_hh);

    cudaEventRecord(ev_join, s_gemm);
    cudaStreamWaitEvent(0, ev_join, 0);

    loss_kernel<<<T_STEPS, 256>>>(ys32);
    reduce_kernel<<<1, 256>>>(out);
}

// round 11
// speedup vs baseline: 1.4240x; 1.4240x over previous
#include <cuda_runtime.h>
#include <cuda_bf16.h>
#include <cstdint>

// ---------------------------------------------------------------------------
// CharRNN: T=16384 LSTM steps, E=H=1024, loss = sum_t (logsumexp(h_t) - h_t[y_t])
//
// Kernel 0: init (set sync-buffer phase bits, detect ys dtype)
// Kernel 1: xg = Xs @ W_ih^T + b   (fp32 GEMM, f32x2 packed FMA, serial)
// Kernel 2: persistent recurrence, 128 CTAs; h published as fp32 with a
//           1-bit phase in the mantissa LSB (4KB exchange, fence-free);
//           weights in registers; f32x2 dots; lane-parallel tanh gates.
// Kernel 3: parallel per-timestep loss   Kernel 4: deterministic reduction
// ---------------------------------------------------------------------------

#define T_STEPS 16384
#define E_DIM   1024
#define H_DIM   1024
#define NWORK   128

typedef unsigned long long ull;

__device__ float    g_xg[(size_t)T_STEPS * 4 * H_DIM];   // 256 MB
__device__ float    g_hist[(size_t)T_STEPS * H_DIM];     // 64 MB
__device__ unsigned g_syncf[2][H_DIM];                   // h with LSB phase, 2x4KB
__device__ float    g_loss[T_STEPS];
__device__ int      g_is64;

// ---------------------------------------------------------------------------
__device__ __forceinline__ ull ffma2(ull a, ull b, ull c)
{
    ull d;
    asm("fma.rn.f32x2 %0, %1, %2, %3;" : "=l"(d) : "l"(a), "l"(b), "l"(c));
    return d;
}
__device__ __forceinline__ float2 unpack2(ull v)
{
    float2 f;
    asm("mov.b64 {%0, %1}, %2;" : "=f"(f.x), "=f"(f.y) : "l"(v));
    return f;
}
__device__ __forceinline__ ull pack2(float lo, float hi)
{
    ull v;
    asm("mov.b64 %0, {%1, %2};" : "=l"(v) : "f"(lo), "f"(hi));
    return v;
}
__device__ __forceinline__ float tanh_apx(float x)
{
    float r;
    asm("tanh.approx.f32 %0, %1;" : "=f"(r) : "f"(x));
    return r;
}

// ---------------------------------------------------------------------------
// init: set sync phase bits (buf0 LSB=0, buf1 LSB=1) + detect ys dtype
// first use of buf1 is step s=1 (phase 0) -> stale LSB must be 1; buf0's
// first use is s=2 (phase 1) -> stale LSB must be 0.
// ---------------------------------------------------------------------------
__global__ void init_kernel(const int* __restrict__ ys32)
{
    const int tid = threadIdx.x;
    for (int i = tid; i < H_DIM; i += 256) {
        g_syncf[0][i] = 0u;
        g_syncf[1][i] = 1u;
    }
    __shared__ int any_odd;
    if (tid == 0) any_odd = 0;
    __syncthreads();
    int odd = 0;
    for (int i = tid; i < T_STEPS / 2; i += 256)
        odd |= (ys32[2 * i + 1] != 0);
    if (odd) any_odd = 1;
    __syncthreads();
    if (tid == 0) g_is64 = !any_odd;
}

// ---------------------------------------------------------------------------
// GEMM: C[M=T][N=4096] = X[M][K=1024] * W[N][K]^T + (b1+b2), f32x2 inner loop
// ---------------------------------------------------------------------------
__global__ __launch_bounds__(256, 2) void xg_gemm_kernel(
    const float* __restrict__ X, const float* __restrict__ W,
    const float* __restrict__ b1, const float* __restrict__ b2)
{
    __shared__ float As[8][128];
    __shared__ float Bs[8][128];

    const int bm = blockIdx.y * 128;
    const int bn = blockIdx.x * 128;
    const int tid = threadIdx.x;
    const int tr = (tid >> 4) << 3;
    const int tc = (tid & 15) << 3;
    const int lr = tid >> 1;
    const int lc = (tid & 1) << 2;

    const float* Ag = X + (size_t)(bm + lr) * E_DIM + lc;
    const float* Bg = W + (size_t)(bn + lr) * E_DIM + lc;

    ull acc2[8][4];
#pragma unroll
    for (int i = 0; i < 8; i++)
#pragma unroll
        for (int j = 0; j < 4; j++) acc2[i][j] = 0ull;

    for (int k0 = 0; k0 < E_DIM; k0 += 8) {
        float4 av = *(const float4*)(Ag + k0);
        float4 bv = *(const float4*)(Bg + k0);
        __syncthreads();
        As[lc + 0][lr] = av.x; As[lc + 1][lr] = av.y;
        As[lc + 2][lr] = av.z; As[lc + 3][lr] = av.w;
        Bs[lc + 0][lr] = bv.x; Bs[lc + 1][lr] = bv.y;
        Bs[lc + 2][lr] = bv.z; Bs[lc + 3][lr] = bv.w;
        __syncthreads();
#pragma unroll
        for (int kk = 0; kk < 8; kk++) {
            float4 b0 = *(const float4*)&Bs[kk][tc];
            float4 b1v = *(const float4*)&Bs[kk][tc + 4];
            ull b2r[4];
            b2r[0] = pack2(b0.x, b0.y); b2r[1] = pack2(b0.z, b0.w);
            b2r[2] = pack2(b1v.x, b1v.y); b2r[3] = pack2(b1v.z, b1v.w);
            float4 a0 = *(const float4*)&As[kk][tr];
            float4 a1v = *(const float4*)&As[kk][tr + 4];
            float ar[8] = {a0.x, a0.y, a0.z, a0.w, a1v.x, a1v.y, a1v.z, a1v.w};
#pragma unroll
            for (int i = 0; i < 8; i++) {
                ull a2 = pack2(ar[i], ar[i]);
#pragma unroll
                for (int j = 0; j < 4; j++)
                    acc2[i][j] = ffma2(a2, b2r[j], acc2[i][j]);
            }
        }
    }

    float bias[8];
#pragma unroll
    for (int j = 0; j < 8; j++) bias[j] = b1[bn + tc + j] + b2[bn + tc + j];

#pragma unroll
    for (int i = 0; i < 8; i++) {
        size_t row = (size_t)(bm + tr + i);
        float* cp = g_xg + row * (4 * H_DIM) + bn + tc;
        float2 p0 = unpack2(acc2[i][0]), p1 = unpack2(acc2[i][1]);
        float2 p2 = unpack2(acc2[i][2]), p3 = unpack2(acc2[i][3]);
        float4 v0, v1;
        v0.x = p0.x + bias[0]; v0.y = p0.y + bias[1];
        v0.z = p1.x + bias[2]; v0.w = p1.y + bias[3];
        v1.x = p2.x + bias[4]; v1.y = p2.y + bias[5];
        v1.z = p3.x + bias[6]; v1.w = p3.y + bias[7];
        *(float4*)(cp + 0) = v0;
        *(float4*)(cp + 4) = v1;
    }
}

// ---------------------------------------------------------------------------
// persistent recurrence: 128 CTAs x 256 threads; warp w of CTA b owns h index
// k=b*8+w and gate rows {k,H+k,2H+k,3H+k} in registers.
// Sync: fp32 h with 1-bit phase in mantissa LSB (4KB per buffer).
// ---------------------------------------------------------------------------
__global__ __launch_bounds__(256, 1) void lstm_kernel(const float* __restrict__ W_hh)
{
    const int cta  = blockIdx.x;
    const int tid  = threadIdx.x;
    const int warp = tid >> 5;
    const int lane = tid & 31;
    const int k    = cta * 8 + warp;

    __shared__ float hs[2][H_DIM];          // double-buffered stage

    ull w0[16], w1[16], w2[16], w3[16];
#pragma unroll
    for (int c = 0; c < 8; c++) {
        int col = lane + 32 * c;           // float4 index in row
        ulonglong2 v;
        v = ((const ulonglong2*)(W_hh + (size_t)(0 * H_DIM + k) * H_DIM))[col];
        w0[2 * c] = v.x; w0[2 * c + 1] = v.y;
        v = ((const ulonglong2*)(W_hh + (size_t)(1 * H_DIM + k) * H_DIM))[col];
        w1[2 * c] = v.x; w1[2 * c + 1] = v.y;
        v = ((const ulonglong2*)(W_hh + (size_t)(2 * H_DIM + k) * H_DIM))[col];
        w2[2 * c] = v.x; w2[2 * c + 1] = v.y;
        v = ((const ulonglong2*)(W_hh + (size_t)(3 * H_DIM + k) * H_DIM))[col];
        w3[2 * c] = v.x; w3[2 * c + 1] = v.y;
    }

    float c_state = 0.f;

    // software-pipelined xg load: lane j (j<4) holds gate-j xg for this step
    float xn = 0.f;
    if (lane < 4)
        xn = __ldcs(g_xg + (size_t)lane * H_DIM + k);

    for (int t = 0; t < T_STEPS; t++) {
        float xg_j = xn;
        if (lane < 4 && t + 1 < T_STEPS)
            xn = __ldcs(g_xg + (size_t)(t + 1) * (4 * H_DIM) + (size_t)lane * H_DIM + k);

        float a0 = 0.f, a1 = 0.f, a2 = 0.f, a3 = 0.f;
        if (t > 0) {
            // poll own 4 words (16B) until all LSBs match phase (t>>1)&1
            const unsigned* sb = g_syncf[t & 1];
            const unsigned p = (unsigned)(t >> 1) & 1u;
            unsigned x0, x1, x2, x3;
            for (;;) {
                asm volatile("ld.global.cg.v4.b32 {%0,%1,%2,%3}, [%4];"
                             : "=r"(x0), "=r"(x1), "=r"(x2), "=r"(x3)
                             : "l"(sb + 4 * tid));
                unsigned m = ((x0 ^ p) | (x1 ^ p) | (x2 ^ p) | (x3 ^ p)) & 1u;
                if (m == 0u) break;
            }
            ((uint4*)hs[t & 1])[tid] = make_uint4(x0, x1, x2, x3);
            __syncthreads();   // hs[t&1] ready (single bar per step)

            const ulonglong2* hsv = (const ulonglong2*)hs[t & 1];
            ull p0 = 0, p1 = 0, p2 = 0, p3 = 0;
#pragma unroll
            for (int c = 0; c < 8; c++) {
                ulonglong2 hv = hsv[lane + 32 * c];
                p0 = ffma2(w0[2 * c], hv.x, p0); p0 = ffma2(w0[2 * c + 1], hv.y, p0);
                p1 = ffma2(w1[2 * c], hv.x, p1); p1 = ffma2(w1[2 * c + 1], hv.y, p1);
                p2 = ffma2(w2[2 * c], hv.x, p2); p2 = ffma2(w2[2 * c + 1], hv.y, p2);
                p3 = ffma2(w3[2 * c], hv.x, p3); p3 = ffma2(w3[2 * c + 1], hv.y, p3);
            }
            float2 f;
            f = unpack2(p0); a0 = f.x + f.y;
            f = unpack2(p1); a1 = f.x + f.y;
            f = unpack2(p2); a2 = f.x + f.y;
            f = unpack2(p3); a3 = f.x + f.y;
        }

        // 4x scalar butterfly reductions (independent latency chains)
#pragma unroll
        for (int off = 16; off; off >>= 1) {
            a0 += __shfl_xor_sync(0xffffffffu, a0, off);
            a1 += __shfl_xor_sync(0xffffffffu, a1, off);
            a2 += __shfl_xor_sync(0xffffffffu, a2, off);
            a3 += __shfl_xor_sync(0xffffffffu, a3, off);
        }

        // lane-parallel activations: lane j in {0..3} computes gate j
        float aj = a0;
        aj = (lane == 1) ? a1 : aj;
        aj = (lane == 2) ? a2 : aj;
        aj = (lane == 3) ? a3 : aj;
        float z   = aj + xg_j;
        float arg = (lane == 2) ? z : 0.5f * z;
        float th  = tanh_apx(arg);
        float gte = (lane == 2) ? th : fmaf(0.5f, th, 0.5f);   // sigmoid via tanh

        float gf = __shfl_sync(0xffffffffu, gte, 1);
        float gg = __shfl_sync(0xffffffffu, gte, 2);
        float go = __shfl_sync(0xffffffffu, gte, 3);

        if (lane == 0) {
            c_state = gf * c_state + gte * gg;       // gte == gi on lane 0
            float h = go * tanh_apx(c_state);
            // publish h with phase bit ((t+1)>>1)&1 in the mantissa LSB
            unsigned hb = (__float_as_uint(h) & ~1u) |
                          ((unsigned)((t + 1) >> 1) & 1u);
            __stcg(&g_syncf[(t + 1) & 1][k], hb);
            __stcs(&g_hist[(size_t)t * H_DIM + k], h);
        }
    }
}

// ---------------------------------------------------------------------------
// parallel loss: one CTA per timestep
// ---------------------------------------------------------------------------
__global__ __launch_bounds__(256) void loss_kernel(const int* __restrict__ ys32)
{
    const int t    = blockIdx.x;
    const int tid  = threadIdx.x;
    const int warp = tid >> 5;
    const int lane = tid & 31;
    __shared__ float red[8];

    const float* hrow = g_hist + (size_t)t * H_DIM;
    float4 hv = __ldcs(((const float4*)hrow) + tid);
    float s = __expf(hv.x) + __expf(hv.y) + __expf(hv.z) + __expf(hv.w);
#pragma unroll
    for (int off = 16; off; off >>= 1)
        s += __shfl_xor_sync(0xffffffffu, s, off);
    if (lane == 0) red[warp] = s;
    __syncthreads();
    if (tid == 0) {
        float tot = 0.f;
#pragma unroll
        for (int i = 0; i < 8; i++) tot += red[i];
        int y = g_is64 ? ys32[2 * t] : ys32[t];
        y &= (H_DIM - 1);
        g_loss[t] = logf(tot) - hrow[y];
    }
}

// ---------------------------------------------------------------------------
__global__ __launch_bounds__(256) void reduce_kernel(float* __restrict__ out)
{
    const int tid = threadIdx.x;
    __shared__ double red[256];
    double acc = 0.0;
    for (int i = tid; i < T_STEPS; i += 256)
        acc += (double)g_loss[i];
    red[tid] = acc;
    __syncthreads();
    for (int s = 128; s; s >>= 1) {
        if (tid < s) red[tid] += red[tid + s];
        __syncthreads();
    }
    if (tid == 0) out[0] = (float)red[0];
}

// ---------------------------------------------------------------------------
extern "C" void kernel_launch(void* const* d_in, const int* in_sizes, int n_in,
                              void* d_out, int out_size)
{
    const float* Xs   = (const float*)d_in[0];
    const float* W_ih = (const float*)d_in[1];
    const float* W_hh = (const float*)d_in[2];
    const float* b_ih = (const float*)d_in[3];
    const float* b_hh = (const float*)d_in[4];
    const int*   ys32 = (const int*)d_in[5];
    float* out = (float*)d_out;

    (void)in_sizes; (void)n_in; (void)out_size;

    init_kernel<<<1, 256>>>(ys32);
    dim3 ggrid(4 * H_DIM / 128, T_STEPS / 128);   // (32, 128)
    xg_gemm_kernel<<<ggrid, 256>>>(Xs, W_ih, b_ih, b_hh);
    lstm_kernel<<<NWORK, 256>>>(W_hh);
    loss_kernel<<<T_STEPS, 256>>>(ys32);
    reduce_kernel<<<1, 256>>>(out);
}